// round 8
// baseline (speedup 1.0000x reference)
#include <cuda_runtime.h>

#define NB   128   // batch
#define ND   32    // dims
#define NP   16384 // N0*N1 pairs
#define NCTA 148   // one CTA per SM (one wave -> grid barrier is safe)
#define THREADS 512
#define TILE 56    // pairs per smem tile (compile-time; tail zero-padded)
#define GROUPS 4
#define PPT (TILE/GROUPS)   // 14 pairs per thread per tile
#define PSTRIDE 33 // 32 num + 1 den

typedef unsigned long long u64;

__device__ float g_partial[NCTA * NB * PSTRIDE];
__device__ unsigned int g_arrive;   // monotonic across graph replays

// ---- packed f32x2 helpers (Blackwell FFMA2/FADD2: PTX-only) ----
__device__ __forceinline__ u64 fma2(u64 a, u64 b, u64 c) {
    u64 d;
    asm("fma.rn.f32x2 %0, %1, %2, %3;" : "=l"(d) : "l"(a), "l"(b), "l"(c));
    return d;
}
__device__ __forceinline__ u64 add2(u64 a, u64 b) {
    u64 d;
    asm("add.rn.f32x2 %0, %1, %2;" : "=l"(d) : "l"(a), "l"(b));
    return d;
}
__device__ __forceinline__ u64 pack2(float lo, float hi) {
    u64 d;
    asm("mov.b64 %0, {%1, %2};" : "=l"(d) : "f"(lo), "f"(hi));
    return d;
}
__device__ __forceinline__ void unpack2(u64 v, float& lo, float& hi) {
    asm("mov.b64 {%0, %1}, %2;" : "=f"(lo), "=f"(hi) : "l"(v));
}

// ---------------------------------------------------------------------------
// Single fused kernel: coefficients -> two-pass accumulate -> partials ->
// grid barrier -> per-batch final reduce. All reductions fixed-order.
// ---------------------------------------------------------------------------
__global__ __launch_bounds__(THREADS, 1)
void gmm_all(const float* __restrict__ X,   const float* __restrict__ t_ptr,
             const float* __restrict__ Mu0, const float* __restrict__ Mu1,
             const float* __restrict__ S0,  const float* __restrict__ S1,
             const float* __restrict__ Lam, float* __restrict__ out)
{
    __shared__ __align__(16) float s_p2[TILE * ND];
    __shared__ __align__(16) float s_p1[TILE * ND];
    __shared__ __align__(16) float s_pk[TILE * ND];
    __shared__ __align__(16) float s_pc[TILE * ND];
    __shared__ float s_p0[TILE];
    __shared__ float s_lam[TILE];
    __shared__ float s_red[NB * PSTRIDE];

    const int tid  = threadIdx.x;
    const int wid  = tid >> 5;
    const int lane = tid & 31;
    const int g    = tid >> 7;        // pair group 0..3
    const int b    = tid & (NB - 1);  // batch

    const int cta     = blockIdx.x;
    const int basecnt = NP / NCTA;            // 110
    const int rem     = NP - basecnt * NCTA;  // 104
    const int start   = cta * basecnt + (cta < rem ? cta : rem);
    const int end     = start + basecnt + (cta < rem ? 1 : 0);

    const float t     = t_ptr[0];
    const float omt   = 1.0f - t;
    const float e2    = 0.25f;     // eps^2 (eps = 0.5)
    const float e4    = 0.0625f;   // eps^4
    const float tt    = t * t;
    const float omt2  = omt * omt;
    const float t2omt = 2.0f * t * omt;
    const float e2tot = e2 * t * omt;

    // X row for this thread's batch: 16 packed f32x2 in registers
    u64 xq[16];
    {
        const ulonglong2* xg = (const ulonglong2*)(X + b * ND);
        #pragma unroll
        for (int q = 0; q < 8; q++) {
            const ulonglong2 v = xg[q];
            xq[2*q]   = v.x;
            xq[2*q+1] = v.y;
        }
    }

    float den = 0.0f;
    u64 numq[16];
    #pragma unroll
    for (int q = 0; q < 16; q++) numq[q] = 0ull;

    for (int base = start; base < end; base += TILE) {
        const int np = min(TILE, end - base);

        // ---- coefficient phase: warp per pair, lane per dim (coalesced) ----
        for (int p = wid; p < np; p += THREADS / 32) {
            const int ij = base + p;
            const int i  = ij >> 7;
            const int j  = ij & 127;

            const float lam = Lam[ij];

            const float s0 = S0[i * ND + lane];
            const float s1 = S1[j * ND + lane];
            const float Ds = sqrtf(fmaf(4.0f * s0, s1, e4));
            const float Cs = 0.5f * (Ds - e2);
            const float Sigma = omt2 * s0 + tt * s1 + t2omt * Cs + e2tot;
            const float St = (t * s1 + omt * Cs) - (omt * s0 + t * Cs) - e2 * t;

            const float mu0 = Mu0[i * ND + lane];
            const float mu1 = Mu1[j * ND + lane];
            const float mut = fmaf(t, mu1, omt * mu0);

            const float inv = __fdividef(1.0f, Sigma);
            const float K   = St * inv;
            const float a   = -0.5f * inv;

            s_p2[p * ND + lane] = a;
            s_p1[p * ND + lane] = inv * mut;
            s_pk[p * ND + lane] = K;
            s_pc[p * ND + lane] = (mu1 - mu0) - K * mut;

            float p0 = fmaf(a * mut, mut, -0.5f * __logf(Sigma));
            #pragma unroll
            for (int off = 16; off; off >>= 1)
                p0 += __shfl_xor_sync(0xFFFFFFFFu, p0, off);
            if (lane == 0) { s_p0[p] = p0; s_lam[p] = lam; }
        }
        // zero-pad tail pairs: w will be exactly 0, no NaNs
        for (int p = np + wid; p < TILE; p += THREADS / 32) {
            s_p2[p * ND + lane] = 0.0f;
            s_p1[p * ND + lane] = 0.0f;
            s_pk[p * ND + lane] = 0.0f;
            s_pc[p * ND + lane] = 0.0f;
            if (lane == 0) { s_p0[p] = 0.0f; s_lam[p] = 0.0f; }
        }
        __syncthreads();

        // ---- pass 1: 14 independent logw->exp chains (max ILP) ----
        float w_arr[PPT];
        #pragma unroll
        for (int pp = 0; pp < PPT; pp++) {
            const int p = g + pp * GROUPS;
            const ulonglong2* A2 = (const ulonglong2*)(s_p2 + p * ND);
            const ulonglong2* B2 = (const ulonglong2*)(s_p1 + p * ND);

            u64 l0 = pack2(s_p0[p], 0.0f), l1 = 0ull, l2 = 0ull, l3 = 0ull;
            #pragma unroll
            for (int q = 0; q < 8; q++) {
                const ulonglong2 av = A2[q];
                const ulonglong2 bv = B2[q];
                const u64 t0 = fma2(av.x, xq[2*q],   bv.x);
                const u64 t1 = fma2(av.y, xq[2*q+1], bv.y);
                if (q & 1) {
                    l2 = fma2(t0, xq[2*q],   l2);
                    l3 = fma2(t1, xq[2*q+1], l3);
                } else {
                    l0 = fma2(t0, xq[2*q],   l0);
                    l1 = fma2(t1, xq[2*q+1], l1);
                }
            }
            const u64 s = add2(add2(l0, l1), add2(l2, l3));
            float lo, hi;
            unpack2(s, lo, hi);
            float logw = fminf(fmaxf(lo + hi, -50.0f), 50.0f);
            w_arr[pp] = __expf(logw) * s_lam[p];
        }
        #pragma unroll
        for (int pp = 0; pp < PPT; pp++) den += w_arr[pp];

        // ---- pass 2: pure LDS + FFMA2 stream, no stalls ----
        #pragma unroll
        for (int pp = 0; pp < PPT; pp++) {
            const int p = g + pp * GROUPS;
            const u64 w2 = pack2(w_arr[pp], w_arr[pp]);
            const ulonglong2* K2 = (const ulonglong2*)(s_pk + p * ND);
            const ulonglong2* C2 = (const ulonglong2*)(s_pc + p * ND);
            #pragma unroll
            for (int q = 0; q < 8; q++) {
                const ulonglong2 kv = K2[q];
                const ulonglong2 cv = C2[q];
                const u64 t0 = fma2(kv.x, xq[2*q],   cv.x);
                const u64 t1 = fma2(kv.y, xq[2*q+1], cv.y);
                numq[2*q]   = fma2(t0, w2, numq[2*q]);
                numq[2*q+1] = fma2(t1, w2, numq[2*q+1]);
            }
        }
        __syncthreads();
    }

    // ---- group combine: fixed order g = 0,1,2,3 (deterministic) ----
    for (int gg = 0; gg < GROUPS; gg++) {
        if (g == gg) {
            float* my = s_red + b * PSTRIDE;
            if (gg == 0) {
                #pragma unroll
                for (int q = 0; q < 16; q++) {
                    float lo, hi;
                    unpack2(numq[q], lo, hi);
                    my[2*q]   = lo;
                    my[2*q+1] = hi;
                }
                my[32] = den;
            } else {
                #pragma unroll
                for (int q = 0; q < 16; q++) {
                    float lo, hi;
                    unpack2(numq[q], lo, hi);
                    my[2*q]   += lo;
                    my[2*q+1] += hi;
                }
                my[32] += den;
            }
        }
        __syncthreads();
    }

    // write this CTA's partial to global
    {
        float* gp = g_partial + (size_t)cta * NB * PSTRIDE;
        for (int k = tid; k < NB * PSTRIDE; k += THREADS)
            gp[k] = s_red[k];
    }

    // ---- grid-wide arrival barrier (release-arrive, acquire-spin) ----
    __threadfence();
    __syncthreads();
    if (tid == 0) {
        const unsigned ticket = atomicAdd(&g_arrive, 1u);
        if (cta < NB) {
            const unsigned target = (ticket / NCTA + 1u) * NCTA;
            unsigned v;
            do {
                asm volatile("ld.acquire.gpu.global.u32 %0, [%1];"
                             : "=r"(v) : "l"(&g_arrive));
            } while (v < target);
        }
    }
    if (cta >= NB) return;       // non-reducing CTAs exit after arriving
    __syncthreads();

    // ---- final reduce: this CTA owns batch b2 = cta ----
    {
        const int w2i  = tid >> 5;
        const int ln   = tid & 31;
        const float* bp = g_partial + cta * PSTRIDE;

        float acc[3] = {0.f, 0.f, 0.f};
        const int nn[3] = {w2i, w2i + 16, 32};
        #pragma unroll
        for (int r = 0; r < 3; r++) {
            #pragma unroll
            for (int i = 0; i < 5; i++) {
                const int c = ln + 32 * i;
                if (c < NCTA)
                    acc[r] += __ldcg(bp + (size_t)c * NB * PSTRIDE + nn[r]);
            }
        }
        #pragma unroll
        for (int r = 0; r < 3; r++) {
            #pragma unroll
            for (int off = 16; off; off >>= 1)
                acc[r] += __shfl_xor_sync(0xFFFFFFFFu, acc[r], off);
        }
        __syncthreads();   // s_red reuse: all prior readers done
        if (ln == 0) {
            s_red[nn[0]] = acc[0];
            s_red[nn[1]] = acc[1];
            if (w2i == 0) s_red[32] = acc[2];
        }
    }
    __syncthreads();

    if (tid < ND)
        out[cta * ND + tid] = s_red[tid] / s_red[32];
}

// ---------------------------------------------------------------------------
extern "C" void kernel_launch(void* const* d_in, const int* in_sizes, int n_in,
                              void* d_out, int out_size)
{
    const float* X   = (const float*)d_in[0];
    const float* t   = (const float*)d_in[1];
    const float* Mu0 = (const float*)d_in[2];
    const float* Mu1 = (const float*)d_in[3];
    const float* S0  = (const float*)d_in[4];
    const float* S1  = (const float*)d_in[5];
    const float* Lam = (const float*)d_in[6];
    float* out = (float*)d_out;

    gmm_all<<<NCTA, THREADS>>>(X, t, Mu0, Mu1, S0, S1, Lam, out);
}

// round 9
// speedup vs baseline: 1.0348x; 1.0348x over previous
#include <cuda_runtime.h>

#define NB   128   // batch
#define ND   32    // dims
#define NP   16384 // N0*N1 pairs
#define NCTA 148   // one CTA per SM (one wave -> grid barrier is safe)
#define THREADS 512
#define TILE 56    // pairs per smem tile (compile-time; tail zero-padded)
#define GROUPS 4
#define PPT (TILE/GROUPS)   // 14 pairs per group per tile
#define PSTRIDE 33 // 32 num + 1 den

typedef unsigned long long u64;

__device__ float g_partial[NCTA * NB * PSTRIDE];
__device__ unsigned int g_arrive;   // monotonic across graph replays

// ---- packed f32x2 helpers (Blackwell FFMA2/FADD2: PTX-only) ----
__device__ __forceinline__ u64 fma2(u64 a, u64 b, u64 c) {
    u64 d;
    asm("fma.rn.f32x2 %0, %1, %2, %3;" : "=l"(d) : "l"(a), "l"(b), "l"(c));
    return d;
}
__device__ __forceinline__ u64 add2(u64 a, u64 b) {
    u64 d;
    asm("add.rn.f32x2 %0, %1, %2;" : "=l"(d) : "l"(a), "l"(b));
    return d;
}
__device__ __forceinline__ u64 pack2(float lo, float hi) {
    u64 d;
    asm("mov.b64 %0, {%1, %2};" : "=l"(d) : "f"(lo), "f"(hi));
    return d;
}
__device__ __forceinline__ void unpack2(u64 v, float& lo, float& hi) {
    asm("mov.b64 {%0, %1}, %2;" : "=f"(lo), "=f"(hi) : "l"(v));
}

// ---------------------------------------------------------------------------
// Fused kernel. Accumulate layout: lane = (batch-slot s, dim-quarter q);
// thread owns 4 batches x 8 dims -> each pair's 512B of coefficients is read
// once per QUARTET for 4 batches = 128B/(batch,pair): 4x less smem traffic
// than the broadcast scheme (the measured 33us wall).
// warp w: wb = w&3 (batch block of 32), wg = w>>2 (pair group 0..3).
// thread batches: b_r = wb*32 + r*8 + s, r=0..3. dims: q*8 .. q*8+7.
// logw = quartet shfl-xor sum (commutative pairs -> bit-deterministic).
// ---------------------------------------------------------------------------
__global__ __launch_bounds__(THREADS, 1)
void gmm_all(const float* __restrict__ X,   const float* __restrict__ t_ptr,
             const float* __restrict__ Mu0, const float* __restrict__ Mu1,
             const float* __restrict__ S0,  const float* __restrict__ S1,
             const float* __restrict__ Lam, float* __restrict__ out)
{
    __shared__ __align__(16) float s_p2[TILE * ND];
    __shared__ __align__(16) float s_p1[TILE * ND];
    __shared__ __align__(16) float s_pk[TILE * ND];
    __shared__ __align__(16) float s_pc[TILE * ND];
    __shared__ float s_p0[TILE];
    __shared__ float s_lam[TILE];
    __shared__ float s_red[NB * PSTRIDE];

    const int tid  = threadIdx.x;
    const int wid  = tid >> 5;
    const int lane = tid & 31;

    const int q  = lane & 3;          // dim quarter (0..3)
    const int s  = lane >> 2;         // batch slot in warp (0..7)
    const int wb = wid & 3;           // batch block (0..3)
    const int wg = wid >> 2;          // pair group (0..3)

    const int cta     = blockIdx.x;
    const int basecnt = NP / NCTA;            // 110
    const int rem     = NP - basecnt * NCTA;  // 104
    const int start   = cta * basecnt + (cta < rem ? cta : rem);
    const int end     = start + basecnt + (cta < rem ? 1 : 0);

    const float t     = t_ptr[0];
    const float omt   = 1.0f - t;
    const float e2    = 0.25f;     // eps^2 (eps = 0.5)
    const float e4    = 0.0625f;   // eps^4
    const float tt    = t * t;
    const float omt2  = omt * omt;
    const float t2omt = 2.0f * t * omt;
    const float e2tot = e2 * t * omt;

    // x for 4 batches x 8 dims: 16 packed f32x2
    u64 xq[4][4];
    #pragma unroll
    for (int r = 0; r < 4; r++) {
        const int br = wb * 32 + r * 8 + s;
        const ulonglong2* xg = (const ulonglong2*)(X + br * ND + q * 8);
        const ulonglong2 v0 = xg[0];
        const ulonglong2 v1 = xg[1];
        xq[r][0] = v0.x; xq[r][1] = v0.y;
        xq[r][2] = v1.x; xq[r][3] = v1.y;
    }

    float den[4] = {0.f, 0.f, 0.f, 0.f};
    u64 numq[4][4];
    #pragma unroll
    for (int r = 0; r < 4; r++)
        #pragma unroll
        for (int c = 0; c < 4; c++) numq[r][c] = 0ull;

    for (int base = start; base < end; base += TILE) {
        const int np = min(TILE, end - base);

        // ---- coefficient phase: warp per pair, lane per dim (coalesced) ----
        for (int p = wid; p < np; p += THREADS / 32) {
            const int ij = base + p;
            const int i  = ij >> 7;
            const int j  = ij & 127;

            const float lam = Lam[ij];

            const float s0 = S0[i * ND + lane];
            const float s1 = S1[j * ND + lane];
            const float Ds = sqrtf(fmaf(4.0f * s0, s1, e4));
            const float Cs = 0.5f * (Ds - e2);
            const float Sigma = omt2 * s0 + tt * s1 + t2omt * Cs + e2tot;
            const float St = (t * s1 + omt * Cs) - (omt * s0 + t * Cs) - e2 * t;

            const float mu0 = Mu0[i * ND + lane];
            const float mu1 = Mu1[j * ND + lane];
            const float mut = fmaf(t, mu1, omt * mu0);

            const float inv = __fdividef(1.0f, Sigma);
            const float K   = St * inv;
            const float a   = -0.5f * inv;

            s_p2[p * ND + lane] = a;
            s_p1[p * ND + lane] = inv * mut;
            s_pk[p * ND + lane] = K;
            s_pc[p * ND + lane] = (mu1 - mu0) - K * mut;

            float p0 = fmaf(a * mut, mut, -0.5f * __logf(Sigma));
            #pragma unroll
            for (int off = 16; off; off >>= 1)
                p0 += __shfl_xor_sync(0xFFFFFFFFu, p0, off);
            if (lane == 0) { s_p0[p] = p0; s_lam[p] = lam; }
        }
        // zero-pad tail pairs: lam=0 -> w==0 exactly, no NaNs
        for (int p = np + wid; p < TILE; p += THREADS / 32) {
            s_p2[p * ND + lane] = 0.0f;
            s_p1[p * ND + lane] = 0.0f;
            s_pk[p * ND + lane] = 0.0f;
            s_pc[p * ND + lane] = 0.0f;
            if (lane == 0) { s_p0[p] = 0.0f; s_lam[p] = 0.0f; }
        }
        __syncthreads();

        // ---- accumulate: group wg takes pairs p = wg, wg+4, ... ----
        #pragma unroll 2
        for (int pp = 0; pp < PPT; pp++) {
            const int p   = wg + pp * GROUPS;
            const int off = p * ND + q * 8;

            const ulonglong2 aA = *(const ulonglong2*)(s_p2 + off);
            const ulonglong2 aB = *(const ulonglong2*)(s_p2 + off + 4);
            const ulonglong2 bA = *(const ulonglong2*)(s_p1 + off);
            const ulonglong2 bB = *(const ulonglong2*)(s_p1 + off + 4);
            const float p0  = s_p0[p];
            const float lam = s_lam[p];

            float w_[4];
            #pragma unroll
            for (int r = 0; r < 4; r++) {
                const u64 t0 = fma2(aA.x, xq[r][0], bA.x);
                const u64 t1 = fma2(aA.y, xq[r][1], bA.y);
                const u64 t2 = fma2(aB.x, xq[r][2], bB.x);
                const u64 t3 = fma2(aB.y, xq[r][3], bB.y);
                u64 acc0 = fma2(t0, xq[r][0], 0ull);
                u64 acc1 = fma2(t1, xq[r][1], 0ull);
                acc0 = fma2(t2, xq[r][2], acc0);
                acc1 = fma2(t3, xq[r][3], acc1);
                float lo, hi;
                unpack2(add2(acc0, acc1), lo, hi);
                float part = lo + hi;                       // this quarter
                part += __shfl_xor_sync(0xFFFFFFFFu, part, 1);
                part += __shfl_xor_sync(0xFFFFFFFFu, part, 2);
                const float logw = fminf(fmaxf(part + p0, -50.0f), 50.0f);
                w_[r] = __expf(logw) * lam;
                den[r] += w_[r];
            }

            const ulonglong2 kA = *(const ulonglong2*)(s_pk + off);
            const ulonglong2 kB = *(const ulonglong2*)(s_pk + off + 4);
            const ulonglong2 cA = *(const ulonglong2*)(s_pc + off);
            const ulonglong2 cB = *(const ulonglong2*)(s_pc + off + 4);
            #pragma unroll
            for (int r = 0; r < 4; r++) {
                const u64 w2 = pack2(w_[r], w_[r]);
                numq[r][0] = fma2(fma2(kA.x, xq[r][0], cA.x), w2, numq[r][0]);
                numq[r][1] = fma2(fma2(kA.y, xq[r][1], cA.y), w2, numq[r][1]);
                numq[r][2] = fma2(fma2(kB.x, xq[r][2], cB.x), w2, numq[r][2]);
                numq[r][3] = fma2(fma2(kB.y, xq[r][3], cB.y), w2, numq[r][3]);
            }
        }
        __syncthreads();
    }

    // ---- group combine: fixed order wg = 0,1,2,3 (deterministic) ----
    for (int gg = 0; gg < GROUPS; gg++) {
        if (wg == gg) {
            #pragma unroll
            for (int r = 0; r < 4; r++) {
                const int br = wb * 32 + r * 8 + s;
                float* my = s_red + br * PSTRIDE + q * 8;
                float f[8];
                unpack2(numq[r][0], f[0], f[1]);
                unpack2(numq[r][1], f[2], f[3]);
                unpack2(numq[r][2], f[4], f[5]);
                unpack2(numq[r][3], f[6], f[7]);
                if (gg == 0) {
                    #pragma unroll
                    for (int k = 0; k < 8; k++) my[k] = f[k];
                    if (q == 0) s_red[br * PSTRIDE + 32] = den[r];
                } else {
                    #pragma unroll
                    for (int k = 0; k < 8; k++) my[k] += f[k];
                    if (q == 0) s_red[br * PSTRIDE + 32] += den[r];
                }
            }
        }
        __syncthreads();
    }

    // write this CTA's partial to global
    {
        float* gp = g_partial + (size_t)cta * NB * PSTRIDE;
        for (int k = tid; k < NB * PSTRIDE; k += THREADS)
            gp[k] = s_red[k];
    }

    // ---- grid-wide arrival barrier (release-arrive, acquire-spin) ----
    __threadfence();
    __syncthreads();
    if (tid == 0) {
        const unsigned ticket = atomicAdd(&g_arrive, 1u);
        if (cta < NB) {
            const unsigned target = (ticket / NCTA + 1u) * NCTA;
            unsigned v;
            do {
                asm volatile("ld.acquire.gpu.global.u32 %0, [%1];"
                             : "=r"(v) : "l"(&g_arrive));
            } while (v < target);
        }
    }
    if (cta >= NB) return;       // non-reducing CTAs exit after arriving
    __syncthreads();

    // ---- final reduce: this CTA owns batch = cta ----
    {
        const int w2i = tid >> 5;
        const int ln  = tid & 31;
        const float* bp = g_partial + cta * PSTRIDE;

        float acc[3] = {0.f, 0.f, 0.f};
        const int nn[3] = {w2i, w2i + 16, 32};
        #pragma unroll
        for (int r = 0; r < 3; r++) {
            #pragma unroll
            for (int i = 0; i < 5; i++) {
                const int c = ln + 32 * i;
                if (c < NCTA)
                    acc[r] += __ldcg(bp + (size_t)c * NB * PSTRIDE + nn[r]);
            }
        }
        #pragma unroll
        for (int r = 0; r < 3; r++) {
            #pragma unroll
            for (int off = 16; off; off >>= 1)
                acc[r] += __shfl_xor_sync(0xFFFFFFFFu, acc[r], off);
        }
        __syncthreads();   // s_red reuse: all prior readers done
        if (ln == 0) {
            s_red[nn[0]] = acc[0];
            s_red[nn[1]] = acc[1];
            if (w2i == 0) s_red[32] = acc[2];
        }
    }
    __syncthreads();

    if (tid < ND)
        out[cta * ND + tid] = s_red[tid] / s_red[32];
}

// ---------------------------------------------------------------------------
extern "C" void kernel_launch(void* const* d_in, const int* in_sizes, int n_in,
                              void* d_out, int out_size)
{
    const float* X   = (const float*)d_in[0];
    const float* t   = (const float*)d_in[1];
    const float* Mu0 = (const float*)d_in[2];
    const float* Mu1 = (const float*)d_in[3];
    const float* S0  = (const float*)d_in[4];
    const float* S1  = (const float*)d_in[5];
    const float* Lam = (const float*)d_in[6];
    float* out = (float*)d_out;

    gmm_all<<<NCTA, THREADS>>>(X, t, Mu0, Mu1, S0, S1, Lam, out);
}